// round 14
// baseline (speedup 1.0000x reference)
#include <cuda_runtime.h>
#include <cuda_fp16.h>
#include <cstdint>

// ---------------------------------------------------------------------------
// Scratch (no allocation allowed -> __device__ globals)
// ---------------------------------------------------------------------------
#define NMAX 100352
#define EMAX 1600000
static __device__ float g_y0 [(size_t)NMAX * 128];
static __device__ float g_y1 [(size_t)NMAX * 128];
static __device__ float g_num[1024];
static __device__ int   g_cnt[1024];
// CSR scratch
static __device__ int   g_deg [NMAX];
static __device__ int   g_excl[NMAX];
static __device__ int   g_bsum[512];
static __device__ int   g_rowp[NMAX + 1];
static __device__ int   g_off [NMAX];
static __device__ int   g_ssrc[EMAX];
static __device__ float g_sw  [EMAX];

// ---------------------------------------------------------------------------
// CSR build: histogram by dst -> exclusive scan -> fill
// ---------------------------------------------------------------------------
__global__ void k_zero_int(int* __restrict__ p, int n) {
    int i = blockIdx.x * blockDim.x + threadIdx.x;
    if (i < n) p[i] = 0;
}

__global__ void k_hist(const int* __restrict__ ei, int E, int* __restrict__ deg) {
    int e = blockIdx.x * blockDim.x + threadIdx.x;
    if (e < E) atomicAdd(&deg[__ldg(ei + E + e)], 1);
}

__global__ void k_scan_block(const int* __restrict__ deg, int* __restrict__ excl,
                             int* __restrict__ bsum, int N) {
    __shared__ int s[256];
    int t = threadIdx.x;
    int i = blockIdx.x * 256 + t;
    int v = (i < N) ? deg[i] : 0;
    s[t] = v;
    __syncthreads();
#pragma unroll
    for (int d = 1; d < 256; d <<= 1) {
        int add = (t >= d) ? s[t - d] : 0;
        __syncthreads();
        s[t] += add;
        __syncthreads();
    }
    if (i < N) excl[i] = s[t] - v;
    if (t == 255) bsum[blockIdx.x] = s[255];
}

__global__ void k_scan_sums(int* __restrict__ bsum, int nb) {
    __shared__ int s[512];
    int t = threadIdx.x;
    int v = (t < nb) ? bsum[t] : 0;
    s[t] = v;
    __syncthreads();
#pragma unroll
    for (int d = 1; d < 512; d <<= 1) {
        int add = (t >= d) ? s[t - d] : 0;
        __syncthreads();
        s[t] += add;
        __syncthreads();
    }
    if (t < nb) bsum[t] = s[t] - v;
}

__global__ void k_scan_add(const int* __restrict__ excl, const int* __restrict__ bsum,
                           int* __restrict__ rowp, int* __restrict__ off, int N, int E) {
    int i = blockIdx.x * blockDim.x + threadIdx.x;
    if (i < N) {
        int r = excl[i] + bsum[i >> 8];
        rowp[i] = r;
        off[i] = r;
    }
    if (i == 0) rowp[N] = E;
}

__global__ void k_fill(const int* __restrict__ ei, const float* __restrict__ ew, int E,
                       int* __restrict__ off, int* __restrict__ ssrc, float* __restrict__ sw) {
    int e = blockIdx.x * blockDim.x + threadIdx.x;
    if (e >= E) return;
    int d = __ldg(ei + E + e);
    int p = atomicAdd(&off[d], 1);
    ssrc[p] = __ldg(ei + e);
    sw[p] = __ldg(ew + e);
}

// ---------------------------------------------------------------------------
// FP16 hi/lo split helpers (3-term emulated fp32 MMA)
// ---------------------------------------------------------------------------
__device__ __forceinline__ uint32_t pack_hi(float a, float b, float& ra, float& rb) {
    __half ha = __float2half_rn(a), hb = __float2half_rn(b);
    ra = a - __half2float(ha);
    rb = b - __half2float(hb);
    __half2 p = __halves2half2(ha, hb);
    return *(uint32_t*)&p;
}
__device__ __forceinline__ uint32_t pack_lo(float a, float b) {
    __half2 p = __halves2half2(__float2half_rn(a), __float2half_rn(b));
    return *(uint32_t*)&p;
}

__device__ __forceinline__ void mma_f16(float* c, const uint32_t* a, const uint32_t* b) {
    asm volatile(
        "mma.sync.aligned.m16n8k16.row.col.f32.f16.f16.f32 "
        "{%0,%1,%2,%3}, {%4,%5,%6,%7}, {%8,%9}, {%0,%1,%2,%3};"
        : "+f"(c[0]), "+f"(c[1]), "+f"(c[2]), "+f"(c[3])
        : "r"(a[0]), "r"(a[1]), "r"(a[2]), "r"(a[3]), "r"(b[0]), "r"(b[1]));
}

// ---------------------------------------------------------------------------
// FUSED GraphConv layer kernel:
//   out[n,:] = W1 @ (sum_{e in CSR row n} w_e * gx[src_e]) + W2 @ A2[n] + bias
// Phase A: each block gather-aggregates its 128 nodes' rows in fp32 registers
//          and stores them as hi/lo fp16 into PERSISTENT smem (A1).
// Phase B: dual-GEMM mainloop; A1 tiles read from persistent smem, A2/W tiles
//          streamed through a single smem stage with register prefetch
//          (ldg of tile kt+1 issued before MMAs of tile kt).
// SMEM = 90KB (K1=128) -> 2 CTAs/SM: gather-phase CTAs overlap MMA-phase CTAs,
// so L2 (gather) and tensor pipes run concurrently chip-wide.
// ---------------------------------------------------------------------------
template <int K1>
__global__ void __launch_bounds__(256, 2)
k_fused(const float* __restrict__ gx,     // gather source [N, K1]
        const int* __restrict__ rowp, const int* __restrict__ ssrc,
        const float* __restrict__ sw,
        const float* __restrict__ A2,     // root path input [N, K1]
        const float* __restrict__ W1, const float* __restrict__ W2,  // [128, K1]
        const float* __restrict__ bias, float* __restrict__ out, int M) {
    constexpr int BM = 128, BN = 128, LDU = 12;
    constexpr int K = 2 * K1;
    constexpr int NT = K / 16;
    constexpr int A1T = K1 / 16;            // tiles served from persistent A1
    constexpr int LDA = K1 + 4;             // u32 stride of an A1 row (hi | lo | pad)

    extern __shared__ uint32_t smu[];
    uint32_t* Wh  = smu;                    // [128][LDU] stage
    uint32_t* Wl  = Wh  + 128 * LDU;
    uint32_t* A2h = Wl  + 128 * LDU;
    uint32_t* A2l = A2h + 128 * LDU;
    uint32_t* A1  = A2l + 128 * LDU;        // [128][LDA] persistent

    const int tid  = threadIdx.x;
    const int wid  = tid >> 5;
    const int lane = tid & 31;
    const int gid  = lane >> 2;
    const int tg   = lane & 3;
    const int m0   = blockIdx.x * BM;
    const int wm0  = (wid & 3) * 32;
    const int wn0  = (wid >> 2) * 64;

    // ---------------- Phase A: gather-aggregate into A1 --------------------
    {
        constexpr int LPR = K1 / 4;         // lanes per row (32 or 16)
        constexpr int RPW = 32 / LPR;       // rows per warp step (1 or 2)
        const int sub = lane / LPR;
        const int l   = lane % LPR;
        for (int r = wid * RPW + sub; r < BM; r += 8 * RPW) {
            int n = m0 + r;
            float4 a0 = make_float4(0.f, 0.f, 0.f, 0.f);
            float4 a1 = make_float4(0.f, 0.f, 0.f, 0.f);
            if (n < M) {
                int e = __ldg(rowp + n), end = __ldg(rowp + n + 1);
                for (; e + 1 < end; e += 2) {
                    int s0 = __ldg(ssrc + e),  s1 = __ldg(ssrc + e + 1);
                    float w0 = __ldg(sw + e),  w1 = __ldg(sw + e + 1);
                    float4 v0 = __ldg((const float4*)(gx + (size_t)s0 * K1) + l);
                    float4 v1 = __ldg((const float4*)(gx + (size_t)s1 * K1) + l);
                    a0.x += w0 * v0.x; a0.y += w0 * v0.y; a0.z += w0 * v0.z; a0.w += w0 * v0.w;
                    a1.x += w1 * v1.x; a1.y += w1 * v1.y; a1.z += w1 * v1.z; a1.w += w1 * v1.w;
                }
                if (e < end) {
                    int s0 = __ldg(ssrc + e);
                    float w0 = __ldg(sw + e);
                    float4 v0 = __ldg((const float4*)(gx + (size_t)s0 * K1) + l);
                    a0.x += w0 * v0.x; a0.y += w0 * v0.y; a0.z += w0 * v0.z; a0.w += w0 * v0.w;
                }
                a0.x += a1.x; a0.y += a1.y; a0.z += a1.z; a0.w += a1.w;
            }
            float r0, r1, r2, r3;
            uint32_t h0 = pack_hi(a0.x, a0.y, r0, r1);
            uint32_t h1 = pack_hi(a0.z, a0.w, r2, r3);
            *(uint2*)&A1[r * LDA + 2 * l]            = make_uint2(h0, h1);
            *(uint2*)&A1[r * LDA + K1 / 2 + 2 * l]   = make_uint2(pack_lo(r0, r1), pack_lo(r2, r3));
        }
    }

    // ---------------- Phase B: dual-GEMM mainloop --------------------------
    float acc[2][8][4];
#pragma unroll
    for (int i = 0; i < 2; i++)
#pragma unroll
        for (int j = 0; j < 8; j++)
#pragma unroll
            for (int c = 0; c < 4; c++) acc[i][j][c] = 0.f;

    float4 ra[2], rw[2];

    auto ldgT = [&](int kt) {
        int kb = kt * 16;
        const float* W = (kb < K1) ? W1 : W2;
        int ko = (kb < K1) ? kb : kb - K1;
#pragma unroll
        for (int i = 0; i < 2; i++) {
            int lin = tid + i * 256;
            int nrow = lin >> 2, kv = (lin & 3) * 4;
            rw[i] = __ldg((const float4*)(W + (size_t)nrow * K1 + ko + kv));
        }
        if (kb >= K1) {
            int ko2 = kb - K1;
#pragma unroll
            for (int i = 0; i < 2; i++) {
                int lin = tid + i * 256;
                int m = lin >> 2, kv = (lin & 3) * 4;
                ra[i] = make_float4(0.f, 0.f, 0.f, 0.f);
                int mg = m0 + m;
                if (mg < M) ra[i] = __ldg((const float4*)(A2 + (size_t)mg * K1 + ko2 + kv));
            }
        }
    };

    auto stsT = [&](int kt) {
        int kb = kt * 16;
#pragma unroll
        for (int i = 0; i < 2; i++) {
            int lin = tid + i * 256;
            int nrow = lin >> 2, kp = (lin & 3) * 2;
            float r0, r1, r2, r3;
            uint32_t h0 = pack_hi(rw[i].x, rw[i].y, r0, r1);
            uint32_t h1 = pack_hi(rw[i].z, rw[i].w, r2, r3);
            *(uint2*)&Wh[nrow * LDU + kp] = make_uint2(h0, h1);
            *(uint2*)&Wl[nrow * LDU + kp] = make_uint2(pack_lo(r0, r1), pack_lo(r2, r3));
        }
        if (kb >= K1) {
#pragma unroll
            for (int i = 0; i < 2; i++) {
                int lin = tid + i * 256;
                int m = lin >> 2, kp = (lin & 3) * 2;
                float r0, r1, r2, r3;
                uint32_t h0 = pack_hi(ra[i].x, ra[i].y, r0, r1);
                uint32_t h1 = pack_hi(ra[i].z, ra[i].w, r2, r3);
                *(uint2*)&A2h[m * LDU + kp] = make_uint2(h0, h1);
                *(uint2*)&A2l[m * LDU + kp] = make_uint2(pack_lo(r0, r1), pack_lo(r2, r3));
            }
        }
    };

    ldgT(0);
    for (int kt = 0; kt < NT; kt++) {
        __syncthreads();                 // stage free (also gather barrier at kt=0)
        stsT(kt);
        __syncthreads();                 // stage ready
        if (kt + 1 < NT) ldgT(kt + 1);   // prefetch next tile into regs

        uint32_t afh[2][4], afl[2][4];
        if (kt < A1T) {
#pragma unroll
            for (int mt = 0; mt < 2; mt++) {
                int mr = wm0 + mt * 16 + gid;
                int b0 = mr * LDA + kt * 8;
                int b1 = (mr + 8) * LDA + kt * 8;
                afh[mt][0] = A1[b0 + tg];
                afh[mt][1] = A1[b1 + tg];
                afh[mt][2] = A1[b0 + tg + 4];
                afh[mt][3] = A1[b1 + tg + 4];
                afl[mt][0] = A1[b0 + K1 / 2 + tg];
                afl[mt][1] = A1[b1 + K1 / 2 + tg];
                afl[mt][2] = A1[b0 + K1 / 2 + tg + 4];
                afl[mt][3] = A1[b1 + K1 / 2 + tg + 4];
            }
        } else {
#pragma unroll
            for (int mt = 0; mt < 2; mt++) {
                int mr = wm0 + mt * 16 + gid;
                afh[mt][0] = A2h[(mr)     * LDU + tg];
                afh[mt][1] = A2h[(mr + 8) * LDU + tg];
                afh[mt][2] = A2h[(mr)     * LDU + tg + 4];
                afh[mt][3] = A2h[(mr + 8) * LDU + tg + 4];
                afl[mt][0] = A2l[(mr)     * LDU + tg];
                afl[mt][1] = A2l[(mr + 8) * LDU + tg];
                afl[mt][2] = A2l[(mr)     * LDU + tg + 4];
                afl[mt][3] = A2l[(mr + 8) * LDU + tg + 4];
            }
        }
#pragma unroll
        for (int nt = 0; nt < 8; nt++) {
            int n = wn0 + nt * 8 + gid;
            uint32_t bh[2], bl[2];
            bh[0] = Wh[n * LDU + tg];
            bh[1] = Wh[n * LDU + tg + 4];
            bl[0] = Wl[n * LDU + tg];
            bl[1] = Wl[n * LDU + tg + 4];
#pragma unroll
            for (int mt = 0; mt < 2; mt++) {
                mma_f16(acc[mt][nt], afh[mt], bh);
                mma_f16(acc[mt][nt], afh[mt], bl);
                mma_f16(acc[mt][nt], afl[mt], bh);
            }
        }
    }

    // Epilogue: bias + store fp32
#pragma unroll
    for (int mt = 0; mt < 2; mt++) {
        int r0 = m0 + wm0 + mt * 16 + gid;
#pragma unroll
        for (int nt = 0; nt < 8; nt++) {
            int col = wn0 + nt * 8 + 2 * tg;
            float b0v = __ldg(bias + col);
            float b1v = __ldg(bias + col + 1);
            if (r0 < M)
                *(float2*)(out + (size_t)r0 * BN + col) =
                    make_float2(acc[mt][nt][0] + b0v, acc[mt][nt][1] + b1v);
            if (r0 + 8 < M)
                *(float2*)(out + (size_t)(r0 + 8) * BN + col) =
                    make_float2(acc[mt][nt][2] + b0v, acc[mt][nt][3] + b1v);
        }
    }
}

// ---------------------------------------------------------------------------
// Fused readout GEMM (BN=64, K=128, no aggregate path):
//   per-row dot(relu(row @ Wr1^T + br1), Wr2) -> per-graph atomic sums.
// Double-buffered streaming (as in previous rounds).
// ---------------------------------------------------------------------------
__global__ void __launch_bounds__(256, 1)
k_readout(const float* __restrict__ A1,
          const float* __restrict__ W1,
          const float* __restrict__ bias,
          int M,
          const float* __restrict__ Wr2v, const int* __restrict__ batchv) {
    constexpr int BN = 64, BM = 128, K1 = 128, LDU = 12;
    constexpr int STAGE = (BM + BN) * 2 * LDU;
    constexpr int NT_ = K1 / 16;

    extern __shared__ uint32_t smu[];
    const int tid  = threadIdx.x;
    const int wid  = tid >> 5;
    const int lane = tid & 31;
    const int gid  = lane >> 2;
    const int tg   = lane & 3;
    const int m0   = blockIdx.x * BM;
    const int wm0  = wid * 16;

    float acc[8][4];
#pragma unroll
    for (int j = 0; j < 8; j++)
#pragma unroll
        for (int c = 0; c < 4; c++) acc[j][c] = 0.f;

    float4 ra[2], rw[1];

    auto ldgStage = [&](int kt) {
        int kb = kt * 16;
#pragma unroll
        for (int i = 0; i < 2; i++) {
            int lin = tid + i * 256;
            int m = lin >> 2, kv = (lin & 3) * 4;
            ra[i] = make_float4(0.f, 0.f, 0.f, 0.f);
            int mg = m0 + m;
            if (mg < M) ra[i] = __ldg((const float4*)(A1 + (size_t)mg * K1 + kb + kv));
        }
        if (tid < BN * 4) {
            int n = tid >> 2, kv = (tid & 3) * 4;
            rw[0] = __ldg((const float4*)(W1 + (size_t)n * K1 + kb + kv));
        }
    };

    auto stsStage = [&](int stage) {
        uint32_t* Ah = smu + stage * STAGE;
        uint32_t* Al = Ah + BM * LDU;
        uint32_t* Wh = Al + BM * LDU;
        uint32_t* Wl = Wh + BN * LDU;
#pragma unroll
        for (int i = 0; i < 2; i++) {
            int lin = tid + i * 256;
            int m = lin >> 2, kp = (lin & 3) * 2;
            float r0, r1, r2, r3;
            uint32_t h0 = pack_hi(ra[i].x, ra[i].y, r0, r1);
            uint32_t h1 = pack_hi(ra[i].z, ra[i].w, r2, r3);
            *(uint2*)&Ah[m * LDU + kp] = make_uint2(h0, h1);
            *(uint2*)&Al[m * LDU + kp] = make_uint2(pack_lo(r0, r1), pack_lo(r2, r3));
        }
        if (tid < BN * 4) {
            int n = tid >> 2, kp = (tid & 3) * 2;
            float r0, r1, r2, r3;
            uint32_t h0 = pack_hi(rw[0].x, rw[0].y, r0, r1);
            uint32_t h1 = pack_hi(rw[0].z, rw[0].w, r2, r3);
            *(uint2*)&Wh[n * LDU + kp] = make_uint2(h0, h1);
            *(uint2*)&Wl[n * LDU + kp] = make_uint2(pack_lo(r0, r1), pack_lo(r2, r3));
        }
    };

    ldgStage(0);
    stsStage(0);

    for (int kt = 0; kt < NT_; kt++) {
        __syncthreads();
        if (kt + 1 < NT_) ldgStage(kt + 1);

        const uint32_t* Ah = smu + (kt & 1) * STAGE;
        const uint32_t* Al = Ah + BM * LDU;
        const uint32_t* Wh = Al + BM * LDU;
        const uint32_t* Wl = Wh + BN * LDU;

        uint32_t afh[4], afl[4];
        int mr = wm0 + gid;
        afh[0] = Ah[(mr)     * LDU + tg];
        afh[1] = Ah[(mr + 8) * LDU + tg];
        afh[2] = Ah[(mr)     * LDU + tg + 4];
        afh[3] = Ah[(mr + 8) * LDU + tg + 4];
        afl[0] = Al[(mr)     * LDU + tg];
        afl[1] = Al[(mr + 8) * LDU + tg];
        afl[2] = Al[(mr)     * LDU + tg + 4];
        afl[3] = Al[(mr + 8) * LDU + tg + 4];
#pragma unroll
        for (int nt = 0; nt < 8; nt++) {
            int n = nt * 8 + gid;
            uint32_t bh[2], bl[2];
            bh[0] = Wh[n * LDU + tg];
            bh[1] = Wh[n * LDU + tg + 4];
            bl[0] = Wl[n * LDU + tg];
            bl[1] = Wl[n * LDU + tg + 4];
            mma_f16(acc[nt], afh, bh);
            mma_f16(acc[nt], afh, bl);
            mma_f16(acc[nt], afl, bh);
        }
        if (kt + 1 < NT_) stsStage((kt + 1) & 1);
    }

    // relu + dot(Wr2) + quad reduce + per-graph atomics
    float part0 = 0.f, part1 = 0.f;
#pragma unroll
    for (int nt = 0; nt < 8; nt++) {
        int col = nt * 8 + 2 * tg;
        float b0v = __ldg(bias + col);
        float b1v = __ldg(bias + col + 1);
        float w0v = __ldg(Wr2v + col);
        float w1v = __ldg(Wr2v + col + 1);
        part0 += fmaxf(acc[nt][0] + b0v, 0.f) * w0v + fmaxf(acc[nt][1] + b1v, 0.f) * w1v;
        part1 += fmaxf(acc[nt][2] + b0v, 0.f) * w0v + fmaxf(acc[nt][3] + b1v, 0.f) * w1v;
    }
    part0 += __shfl_xor_sync(0xffffffffu, part0, 1);
    part0 += __shfl_xor_sync(0xffffffffu, part0, 2);
    part1 += __shfl_xor_sync(0xffffffffu, part1, 1);
    part1 += __shfl_xor_sync(0xffffffffu, part1, 2);
    if (tg == 0) {
        int r0 = m0 + wm0 + gid;
        int r1 = r0 + 8;
        if (r0 < M) {
            int g = __ldg(batchv + r0);
            atomicAdd(&g_num[g], part0);
            atomicAdd(&g_cnt[g], 1);
        }
        if (r1 < M) {
            int g = __ldg(batchv + r1);
            atomicAdd(&g_num[g], part1);
            atomicAdd(&g_cnt[g], 1);
        }
    }
}

// ---------------------------------------------------------------------------
// Tail
// ---------------------------------------------------------------------------
__global__ void k_zero_small() {
    int i = threadIdx.x;
    if (i < 1024) { g_num[i] = 0.f; g_cnt[i] = 0; }
}

__global__ void k_div(const float* __restrict__ br2, float* __restrict__ out) {
    int g = blockIdx.x * blockDim.x + threadIdx.x;
    if (g < 1024) {
        int c = g_cnt[g];
        out[g] = (c > 0) ? (g_num[g] / (float)c + br2[0]) : 0.f;
    }
}

// ---------------------------------------------------------------------------
// Launch
// ---------------------------------------------------------------------------
extern "C" void kernel_launch(void* const* d_in, const int* in_sizes, int n_in,
                              void* d_out, int out_size) {
    const float* x        = (const float*)d_in[0];
    const int*   ei       = (const int*)  d_in[1];
    const float* ew       = (const float*)d_in[2];
    const int*   batch    = (const int*)  d_in[3];
    const float* W_root0  = (const float*)d_in[4];
    const float* W_rel0   = (const float*)d_in[5];
    const float* b0       = (const float*)d_in[6];
    const float* W_root_r = (const float*)d_in[7];
    const float* W_rel_r  = (const float*)d_in[8];
    const float* b_r      = (const float*)d_in[9];
    const float* Wr1      = (const float*)d_in[10];
    const float* br1      = (const float*)d_in[11];
    const float* Wr2      = (const float*)d_in[12];
    const float* br2      = (const float*)d_in[13];

    const int N = in_sizes[0] / 64;   // nodes
    const int E = in_sizes[2];        // edges
    const int L = in_sizes[9] / 128;  // extra GraphConv layers (3)
    (void)n_in; (void)out_size;

    float *y0, *y1, *sw;
    int *deg, *excl, *bsum, *rowp, *off, *ssrc;
    cudaGetSymbolAddress((void**)&y0,   g_y0);
    cudaGetSymbolAddress((void**)&y1,   g_y1);
    cudaGetSymbolAddress((void**)&deg,  g_deg);
    cudaGetSymbolAddress((void**)&excl, g_excl);
    cudaGetSymbolAddress((void**)&bsum, g_bsum);
    cudaGetSymbolAddress((void**)&rowp, g_rowp);
    cudaGetSymbolAddress((void**)&off,  g_off);
    cudaGetSymbolAddress((void**)&ssrc, g_ssrc);
    cudaGetSymbolAddress((void**)&sw,   g_sw);

    // SMEM: stage (4*128*12 u32 = 24576B) + persistent A1 (128*(K1+4) u32)
    const size_t smemF128 = (4 * 128 * 12 + 128 * 132) * 4;  // 92160
    const size_t smemF64  = (4 * 128 * 12 + 128 * 68) * 4;   // 59392
    const size_t smemRO   = 2 * (size_t)(128 + 64) * 2 * 12 * 4;  // 36864
    cudaFuncSetAttribute(k_fused<128>, cudaFuncAttributeMaxDynamicSharedMemorySize, (int)smemF128);
    cudaFuncSetAttribute(k_fused<64>,  cudaFuncAttributeMaxDynamicSharedMemorySize, (int)smemF64);
    cudaFuncSetAttribute(k_readout,    cudaFuncAttributeMaxDynamicSharedMemorySize, (int)smemRO);

    const int mb = (N + 127) / 128;
    const int nb256 = (N + 255) / 256;
    const int eb = (E + 255) / 256;

    // ---- CSR build (by dst) ----
    k_zero_int<<<nb256, 256>>>(deg, N);
    k_hist<<<eb, 256>>>(ei, E, deg);
    k_scan_block<<<nb256, 256>>>(deg, excl, bsum, N);
    k_scan_sums<<<1, 512>>>(bsum, nb256);
    k_scan_add<<<nb256, 256>>>(excl, bsum, rowp, off, N, E);
    k_fill<<<eb, 256>>>(ei, ew, E, off, ssrc, sw);

    // ---- Layer 0 (fused gather + dual GEMM, K1=64) ----
    k_fused<64><<<mb, 256, smemF64>>>(x, rowp, ssrc, sw, x, W_rel0, W_root0, b0, y0, N);

    // ---- Layers 1..L (fused, K1=128) ----
    float* yin = y0;
    float* yout = y1;
    for (int l = 0; l < L; l++) {
        const float* Wrel  = W_rel_r  + (size_t)l * 128 * 128;
        const float* Wroot = W_root_r + (size_t)l * 128 * 128;
        const float* bl    = b_r + (size_t)l * 128;
        k_fused<128><<<mb, 256, smemF128>>>(yin, rowp, ssrc, sw, yin, Wrel, Wroot, bl, yout, N);
        float* t = yin; yin = yout; yout = t;
    }

    // ---- Readout (fused GEMM + ReLU + dot(Wr2) + scatter-mean) ----
    k_zero_small<<<1, 1024>>>();
    k_readout<<<mb, 256, smemRO>>>(yin, Wr1, br1, N, Wr2, batch);
    k_div<<<4, 256>>>(br2, (float*)d_out);
}

// round 15
// speedup vs baseline: 1.5010x; 1.5010x over previous
#include <cuda_runtime.h>
#include <cuda_fp16.h>
#include <cstdint>

// ---------------------------------------------------------------------------
// Scratch (no allocation allowed -> __device__ globals)
// ---------------------------------------------------------------------------
#define NMAX 100352
#define EMAX 1600000
static __device__ float g_agg[(size_t)NMAX * 128];
static __device__ float g_y0 [(size_t)NMAX * 128];
static __device__ float g_y1 [(size_t)NMAX * 128];
static __device__ float g_num[1024];
static __device__ int   g_cnt[1024];
// CSR scratch
static __device__ int   g_deg [NMAX];
static __device__ int   g_excl[NMAX];
static __device__ int   g_bsum[512];
static __device__ int   g_rowp[NMAX + 1];
static __device__ int   g_off [NMAX];
static __device__ int   g_ssrc[EMAX];
static __device__ float g_sw  [EMAX];
// Pre-converted weight planes (hi/lo fp16x2 as u32)
static __device__ uint32_t g_wsc[131072];

// ---------------------------------------------------------------------------
// CSR build: histogram by dst -> exclusive scan -> fill
// ---------------------------------------------------------------------------
__global__ void k_zero_int(int* __restrict__ p, int n) {
    int i = blockIdx.x * blockDim.x + threadIdx.x;
    if (i < n) p[i] = 0;
}

__global__ void k_hist(const int* __restrict__ ei, int E, int* __restrict__ deg) {
    int e = blockIdx.x * blockDim.x + threadIdx.x;
    if (e < E) atomicAdd(&deg[__ldg(ei + E + e)], 1);
}

__global__ void k_scan_block(const int* __restrict__ deg, int* __restrict__ excl,
                             int* __restrict__ bsum, int N) {
    __shared__ int s[256];
    int t = threadIdx.x;
    int i = blockIdx.x * 256 + t;
    int v = (i < N) ? deg[i] : 0;
    s[t] = v;
    __syncthreads();
#pragma unroll
    for (int d = 1; d < 256; d <<= 1) {
        int add = (t >= d) ? s[t - d] : 0;
        __syncthreads();
        s[t] += add;
        __syncthreads();
    }
    if (i < N) excl[i] = s[t] - v;
    if (t == 255) bsum[blockIdx.x] = s[255];
}

__global__ void k_scan_sums(int* __restrict__ bsum, int nb) {
    __shared__ int s[512];
    int t = threadIdx.x;
    int v = (t < nb) ? bsum[t] : 0;
    s[t] = v;
    __syncthreads();
#pragma unroll
    for (int d = 1; d < 512; d <<= 1) {
        int add = (t >= d) ? s[t - d] : 0;
        __syncthreads();
        s[t] += add;
        __syncthreads();
    }
    if (t < nb) bsum[t] = s[t] - v;
}

__global__ void k_scan_add(const int* __restrict__ excl, const int* __restrict__ bsum,
                           int* __restrict__ rowp, int* __restrict__ off, int N, int E) {
    int i = blockIdx.x * blockDim.x + threadIdx.x;
    if (i < N) {
        int r = excl[i] + bsum[i >> 8];
        rowp[i] = r;
        off[i] = r;
    }
    if (i == 0) rowp[N] = E;
}

__global__ void k_fill(const int* __restrict__ ei, const float* __restrict__ ew, int E,
                       int* __restrict__ off, int* __restrict__ ssrc, float* __restrict__ sw) {
    int e = blockIdx.x * blockDim.x + threadIdx.x;
    if (e >= E) return;
    int d = __ldg(ei + E + e);
    int p = atomicAdd(&off[d], 1);
    ssrc[p] = __ldg(ei + e);
    sw[p] = __ldg(ew + e);
}

// ---------------------------------------------------------------------------
// FP16 hi/lo split helpers
// ---------------------------------------------------------------------------
__device__ __forceinline__ uint32_t pack_hi(float a, float b, float& ra, float& rb) {
    __half ha = __float2half_rn(a), hb = __float2half_rn(b);
    ra = a - __half2float(ha);
    rb = b - __half2float(hb);
    __half2 p = __halves2half2(ha, hb);
    return *(uint32_t*)&p;
}
__device__ __forceinline__ uint32_t pack_lo(float a, float b) {
    __half2 p = __halves2half2(__float2half_rn(a), __float2half_rn(b));
    return *(uint32_t*)&p;
}

__device__ __forceinline__ void mma_f16(float* c, const uint32_t* a, const uint32_t* b) {
    asm volatile(
        "mma.sync.aligned.m16n8k16.row.col.f32.f16.f16.f32 "
        "{%0,%1,%2,%3}, {%4,%5,%6,%7}, {%8,%9}, {%0,%1,%2,%3};"
        : "+f"(c[0]), "+f"(c[1]), "+f"(c[2]), "+f"(c[3])
        : "r"(a[0]), "r"(a[1]), "r"(a[2]), "r"(a[3]), "r"(b[0]), "r"(b[1]));
}

// ---------------------------------------------------------------------------
// Weight pre-conversion: pack all weight matrices into hi/lo u32 planes.
// Pair index space:
//   [0, 8192)                : L0 combined [128 rows][K=128] (k<64 rel, else root)
//   [8192, 8192+L*16384)     : layer l combined [128][256] (k<128 rel, else root)
//   [.., +4096)              : readout Wr1 [64][128]
// u32 write offsets: L0 hi@0 lo@8192; layer l hi@16384+l*32768 lo@+16384;
//                    readout hi@16384+L*32768 lo@+4096.
// ---------------------------------------------------------------------------
__global__ void k_wconv(const float* __restrict__ W_rel0, const float* __restrict__ W_root0,
                        const float* __restrict__ W_rel_r, const float* __restrict__ W_root_r,
                        const float* __restrict__ Wr1, uint32_t* __restrict__ ws, int L) {
    int p = blockIdx.x * blockDim.x + threadIdx.x;
    int total = 8192 + L * 16384 + 4096;
    if (p >= total) return;
    float a, b;
    uint32_t hoff, loff;
    if (p < 8192) {
        int row = p >> 6, kp = p & 63, k0 = 2 * kp;
        const float* src = (k0 < 64) ? (W_rel0 + row * 64 + k0) : (W_root0 + row * 64 + k0 - 64);
        a = __ldg(src); b = __ldg(src + 1);
        hoff = p; loff = p + 8192;
    } else if (p < 8192 + L * 16384) {
        int q = p - 8192;
        int l = q / 16384;
        int r = q - l * 16384;
        int row = r >> 7, kp = r & 127, k0 = 2 * kp;
        const float* src = (k0 < 128) ? (W_rel_r + (size_t)l * 16384 + row * 128 + k0)
                                      : (W_root_r + (size_t)l * 16384 + row * 128 + k0 - 128);
        a = __ldg(src); b = __ldg(src + 1);
        hoff = 16384 + l * 32768 + r; loff = hoff + 16384;
    } else {
        int q = p - (8192 + L * 16384);
        int row = q >> 6, kp = q & 63, k0 = 2 * kp;
        const float* src = Wr1 + row * 128 + k0;
        a = __ldg(src); b = __ldg(src + 1);
        hoff = 16384 + L * 32768 + q; loff = hoff + 4096;
    }
    float r0, r1;
    ws[hoff] = pack_hi(a, b, r0, r1);
    ws[loff] = pack_lo(r0, r1);
}

// ---------------------------------------------------------------------------
// Gather aggregation (no atomics): agg[n] = sum_{e in CSR row n} w[e]*x[src[e]]
// ---------------------------------------------------------------------------
__global__ void k_agg128(const float* __restrict__ x, const int* __restrict__ rowp,
                         const int* __restrict__ ssrc, const float* __restrict__ sw,
                         float* __restrict__ agg, int N) {
    int n = blockIdx.x * 4 + (threadIdx.x >> 5);
    if (n >= N) return;
    int lane = threadIdx.x & 31;
    int e = __ldg(rowp + n), end = __ldg(rowp + n + 1);
    float4 a0 = make_float4(0.f, 0.f, 0.f, 0.f);
    float4 a1 = make_float4(0.f, 0.f, 0.f, 0.f);
    for (; e + 1 < end; e += 2) {
        int s0 = __ldg(ssrc + e),     s1 = __ldg(ssrc + e + 1);
        float w0 = __ldg(sw + e),     w1 = __ldg(sw + e + 1);
        float4 v0 = __ldg((const float4*)(x + (size_t)s0 * 128) + lane);
        float4 v1 = __ldg((const float4*)(x + (size_t)s1 * 128) + lane);
        a0.x += w0 * v0.x; a0.y += w0 * v0.y; a0.z += w0 * v0.z; a0.w += w0 * v0.w;
        a1.x += w1 * v1.x; a1.y += w1 * v1.y; a1.z += w1 * v1.z; a1.w += w1 * v1.w;
    }
    if (e < end) {
        int s0 = __ldg(ssrc + e);
        float w0 = __ldg(sw + e);
        float4 v0 = __ldg((const float4*)(x + (size_t)s0 * 128) + lane);
        a0.x += w0 * v0.x; a0.y += w0 * v0.y; a0.z += w0 * v0.z; a0.w += w0 * v0.w;
    }
    a0.x += a1.x; a0.y += a1.y; a0.z += a1.z; a0.w += a1.w;
    *((float4*)(agg + (size_t)n * 128) + lane) = a0;
}

__global__ void k_agg64(const float* __restrict__ x, const int* __restrict__ rowp,
                        const int* __restrict__ ssrc, const float* __restrict__ sw,
                        float* __restrict__ agg, int N) {
    int n = blockIdx.x * 8 + (threadIdx.x >> 4);
    if (n >= N) return;
    int lane = threadIdx.x & 15;
    int e = __ldg(rowp + n), end = __ldg(rowp + n + 1);
    float4 a0 = make_float4(0.f, 0.f, 0.f, 0.f);
    float4 a1 = make_float4(0.f, 0.f, 0.f, 0.f);
    for (; e + 1 < end; e += 2) {
        int s0 = __ldg(ssrc + e),     s1 = __ldg(ssrc + e + 1);
        float w0 = __ldg(sw + e),     w1 = __ldg(sw + e + 1);
        float4 v0 = __ldg((const float4*)(x + (size_t)s0 * 64) + lane);
        float4 v1 = __ldg((const float4*)(x + (size_t)s1 * 64) + lane);
        a0.x += w0 * v0.x; a0.y += w0 * v0.y; a0.z += w0 * v0.z; a0.w += w0 * v0.w;
        a1.x += w1 * v1.x; a1.y += w1 * v1.y; a1.z += w1 * v1.z; a1.w += w1 * v1.w;
    }
    if (e < end) {
        int s0 = __ldg(ssrc + e);
        float w0 = __ldg(sw + e);
        float4 v0 = __ldg((const float4*)(x + (size_t)s0 * 64) + lane);
        a0.x += w0 * v0.x; a0.y += w0 * v0.y; a0.z += w0 * v0.z; a0.w += w0 * v0.w;
    }
    a0.x += a1.x; a0.y += a1.y; a0.z += a1.z; a0.w += a1.w;
    *((float4*)(agg + (size_t)n * 64) + lane) = a0;
}

// ---------------------------------------------------------------------------
// FP16 tensor-core dual GEMM, 3-term hi/lo split (fp32-accurate):
//   out[M, BN] = A1 @ W1^T + A2 @ W2^T + bias   (optional ReLU)
// W comes PRE-CONVERTED as hi/lo u32 planes (row stride KU = K/2 u32) ->
// W path in mainloop is a raw uint4 copy (no cvt ALU, fewer regs).
// A streamed fp32 + converted on the fly. Double-buffered, occupancy 2.
// FIN=true: fused MLP readout tail (relu -> dot Wr2 -> per-graph atomics).
// ---------------------------------------------------------------------------
template <int BN, int MT, bool FIN>
__global__ void __launch_bounds__(256, 2)
k_gemm_tc(const float* __restrict__ A1, int K1,
          const float* __restrict__ A2, int K2,
          const uint32_t* __restrict__ Whi, const uint32_t* __restrict__ Wlo,
          const float* __restrict__ bias, float* __restrict__ out,
          int M, int relu,
          const float* __restrict__ Wr2v, const int* __restrict__ batchv) {
    constexpr int BM = 128, LDU = 12;                   // 8 data u32 + 4 pad
    constexpr int STAGE = (BM + BN) * 2 * LDU;
    const int K = K1 + K2;
    const int KU = K / 2;                               // u32 per W row
    const int NT_ = K / 16;

    extern __shared__ uint32_t smu[];
    const int tid  = threadIdx.x;
    const int wid  = tid >> 5;
    const int lane = tid & 31;
    const int gid  = lane >> 2;
    const int tg   = lane & 3;
    const int m0   = blockIdx.x * BM;

    const int wm0 = (BN == 128) ? ((wid & 3) * 32) : (wid * 16);
    const int wn0 = (BN == 128) ? ((wid >> 2) * 64) : 0;

    float acc[MT][8][4];
#pragma unroll
    for (int i = 0; i < MT; i++)
#pragma unroll
        for (int j = 0; j < 8; j++)
#pragma unroll
            for (int c = 0; c < 4; c++) acc[i][j][c] = 0.f;

    float4 ra[2];
    uint4 rwh, rwl;

    auto ldgStage = [&](int kt) {
        int kb = kt * 16;
        const float* A; int KA, ko;
        if (kb < K1) { A = A1; KA = K1; ko = kb; } else { A = A2; KA = K2; ko = kb - K1; }
#pragma unroll
        for (int i = 0; i < 2; i++) {
            int lin = tid + i * 256;          // 512 float4 = 128 rows x 4
            int m = lin >> 2, kv = (lin & 3) * 4;
            ra[i] = make_float4(0.f, 0.f, 0.f, 0.f);
            int mg = m0 + m;
            if (mg < M) ra[i] = __ldg((const float4*)(A + (size_t)mg * KA + ko + kv));
        }
        if (tid < BN * 2) {
            int row = tid >> 1, half = tid & 1;
            int kbu = kt * 8 + half * 4;
            rwh = __ldg((const uint4*)(Whi + (size_t)row * KU + kbu));
            rwl = __ldg((const uint4*)(Wlo + (size_t)row * KU + kbu));
        }
    };

    auto stsStage = [&](int stage) {
        uint32_t* Ah = smu + stage * STAGE;
        uint32_t* Al = Ah + BM * LDU;
        uint32_t* Wh = Al + BM * LDU;
        uint32_t* Wl = Wh + BN * LDU;
#pragma unroll
        for (int i = 0; i < 2; i++) {
            int lin = tid + i * 256;
            int m = lin >> 2, kp = (lin & 3) * 2;
            float r0, r1, r2, r3;
            uint32_t h0 = pack_hi(ra[i].x, ra[i].y, r0, r1);
            uint32_t h1 = pack_hi(ra[i].z, ra[i].w, r2, r3);
            *(uint2*)&Ah[m * LDU + kp] = make_uint2(h0, h1);
            *(uint2*)&Al[m * LDU + kp] = make_uint2(pack_lo(r0, r1), pack_lo(r2, r3));
        }
        if (tid < BN * 2) {
            int row = tid >> 1, half = tid & 1;
            *(uint4*)&Wh[row * LDU + half * 4] = rwh;
            *(uint4*)&Wl[row * LDU + half * 4] = rwl;
        }
    };

    ldgStage(0);
    stsStage(0);

    for (int kt = 0; kt < NT_; kt++) {
        __syncthreads();
        if (kt + 1 < NT_) ldgStage(kt + 1);

        const uint32_t* Ah = smu + (kt & 1) * STAGE;
        const uint32_t* Al = Ah + BM * LDU;
        const uint32_t* Wh = Al + BM * LDU;
        const uint32_t* Wl = Wh + BN * LDU;

        uint32_t afh[MT][4], afl[MT][4];
#pragma unroll
        for (int mt = 0; mt < MT; mt++) {
            int mr = wm0 + mt * 16 + gid;
            afh[mt][0] = Ah[(mr)     * LDU + tg];
            afh[mt][1] = Ah[(mr + 8) * LDU + tg];
            afh[mt][2] = Ah[(mr)     * LDU + tg + 4];
            afh[mt][3] = Ah[(mr + 8) * LDU + tg + 4];
            afl[mt][0] = Al[(mr)     * LDU + tg];
            afl[mt][1] = Al[(mr + 8) * LDU + tg];
            afl[mt][2] = Al[(mr)     * LDU + tg + 4];
            afl[mt][3] = Al[(mr + 8) * LDU + tg + 4];
        }
#pragma unroll
        for (int nt = 0; nt < 8; nt++) {
            int n = wn0 + nt * 8 + gid;
            uint32_t bh[2], bl[2];
            bh[0] = Wh[n * LDU + tg];
            bh[1] = Wh[n * LDU + tg + 4];
            bl[0] = Wl[n * LDU + tg];
            bl[1] = Wl[n * LDU + tg + 4];
#pragma unroll
            for (int mt = 0; mt < MT; mt++) {
                mma_f16(acc[mt][nt], afh[mt], bh);
                mma_f16(acc[mt][nt], afh[mt], bl);
                mma_f16(acc[mt][nt], afl[mt], bh);
            }
        }
        if (kt + 1 < NT_) stsStage((kt + 1) & 1);
    }

    if constexpr (FIN) {
        float part0 = 0.f, part1 = 0.f;
#pragma unroll
        for (int nt = 0; nt < 8; nt++) {
            int col = nt * 8 + 2 * tg;
            float b0v = __ldg(bias + col);
            float b1v = __ldg(bias + col + 1);
            float w0v = __ldg(Wr2v + col);
            float w1v = __ldg(Wr2v + col + 1);
            part0 += fmaxf(acc[0][nt][0] + b0v, 0.f) * w0v
                   + fmaxf(acc[0][nt][1] + b1v, 0.f) * w1v;
            part1 += fmaxf(acc[0][nt][2] + b0v, 0.f) * w0v
                   + fmaxf(acc[0][nt][3] + b1v, 0.f) * w1v;
        }
        part0 += __shfl_xor_sync(0xffffffffu, part0, 1);
        part0 += __shfl_xor_sync(0xffffffffu, part0, 2);
        part1 += __shfl_xor_sync(0xffffffffu, part1, 1);
        part1 += __shfl_xor_sync(0xffffffffu, part1, 2);
        if (tg == 0) {
            int r0 = m0 + wm0 + gid;
            int r1 = r0 + 8;
            if (r0 < M) {
                int g = __ldg(batchv + r0);
                atomicAdd(&g_num[g], part0);
                atomicAdd(&g_cnt[g], 1);
            }
            if (r1 < M) {
                int g = __ldg(batchv + r1);
                atomicAdd(&g_num[g], part1);
                atomicAdd(&g_cnt[g], 1);
            }
        }
    } else {
#pragma unroll
        for (int mt = 0; mt < MT; mt++) {
            int r0 = m0 + wm0 + mt * 16 + gid;
#pragma unroll
            for (int nt = 0; nt < 8; nt++) {
                int col = wn0 + nt * 8 + 2 * tg;
                float b0v = __ldg(bias + col);
                float b1v = __ldg(bias + col + 1);
                float v0 = acc[mt][nt][0] + b0v;
                float v1 = acc[mt][nt][1] + b1v;
                float v2 = acc[mt][nt][2] + b0v;
                float v3 = acc[mt][nt][3] + b1v;
                if (relu) {
                    v0 = fmaxf(v0, 0.f); v1 = fmaxf(v1, 0.f);
                    v2 = fmaxf(v2, 0.f); v3 = fmaxf(v3, 0.f);
                }
                if (r0 < M)     *(float2*)(out + (size_t)r0 * BN + col)       = make_float2(v0, v1);
                if (r0 + 8 < M) *(float2*)(out + (size_t)(r0 + 8) * BN + col) = make_float2(v2, v3);
            }
        }
    }
}

// ---------------------------------------------------------------------------
// Tail
// ---------------------------------------------------------------------------
__global__ void k_zero_small() {
    int i = threadIdx.x;
    if (i < 1024) { g_num[i] = 0.f; g_cnt[i] = 0; }
}

__global__ void k_div(const float* __restrict__ br2, float* __restrict__ out) {
    int g = blockIdx.x * blockDim.x + threadIdx.x;
    if (g < 1024) {
        int c = g_cnt[g];
        out[g] = (c > 0) ? (g_num[g] / (float)c + br2[0]) : 0.f;
    }
}

// ---------------------------------------------------------------------------
// Launch
// ---------------------------------------------------------------------------
extern "C" void kernel_launch(void* const* d_in, const int* in_sizes, int n_in,
                              void* d_out, int out_size) {
    const float* x        = (const float*)d_in[0];
    const int*   ei       = (const int*)  d_in[1];
    const float* ew       = (const float*)d_in[2];
    const int*   batch    = (const int*)  d_in[3];
    const float* W_root0  = (const float*)d_in[4];
    const float* W_rel0   = (const float*)d_in[5];
    const float* b0       = (const float*)d_in[6];
    const float* W_root_r = (const float*)d_in[7];
    const float* W_rel_r  = (const float*)d_in[8];
    const float* b_r      = (const float*)d_in[9];
    const float* Wr1      = (const float*)d_in[10];
    const float* br1      = (const float*)d_in[11];
    const float* Wr2      = (const float*)d_in[12];
    const float* br2      = (const float*)d_in[13];

    const int N = in_sizes[0] / 64;   // nodes
    const int E = in_sizes[2];        // edges
    const int L = in_sizes[9] / 128;  // extra GraphConv layers (3)
    (void)n_in; (void)out_size;

    float *agg, *y0, *y1, *sw;
    int *deg, *excl, *bsum, *rowp, *off, *ssrc;
    uint32_t* ws;
    cudaGetSymbolAddress((void**)&agg,  g_agg);
    cudaGetSymbolAddress((void**)&y0,   g_y0);
    cudaGetSymbolAddress((void**)&y1,   g_y1);
    cudaGetSymbolAddress((void**)&deg,  g_deg);
    cudaGetSymbolAddress((void**)&excl, g_excl);
    cudaGetSymbolAddress((void**)&bsum, g_bsum);
    cudaGetSymbolAddress((void**)&rowp, g_rowp);
    cudaGetSymbolAddress((void**)&off,  g_off);
    cudaGetSymbolAddress((void**)&ssrc, g_ssrc);
    cudaGetSymbolAddress((void**)&sw,   g_sw);
    cudaGetSymbolAddress((void**)&ws,   g_wsc);

    // Dynamic SMEM: 2 stages * (BM+BN) rows * 2(hi/lo) * 12 u32 * 4B
    const size_t smem128 = 2 * (size_t)(128 + 128) * 2 * 12 * 4;  // 49152
    const size_t smem64  = 2 * (size_t)(128 + 64)  * 2 * 12 * 4;  // 36864
    cudaFuncSetAttribute(k_gemm_tc<128, 2, false>, cudaFuncAttributeMaxDynamicSharedMemorySize, (int)smem128);
    cudaFuncSetAttribute(k_gemm_tc<64, 1, true>,   cudaFuncAttributeMaxDynamicSharedMemorySize, (int)smem64);

    const int mb = (N + 127) / 128;
    const int nb256 = (N + 255) / 256;
    const int eb = (E + 255) / 256;

    // Weight plane offsets in g_wsc (u32)
    uint32_t* w0h = ws;                      // L0: [128][64] u32
    uint32_t* w0l = ws + 8192;
    uint32_t* wrh = ws + 16384;              // layer l: +l*32768, [128][128] u32
    uint32_t* roh = ws + 16384 + (size_t)L * 32768;  // readout: [64][64] u32
    uint32_t* rol = roh + 4096;

    // ---- Weight pre-conversion + CSR build (independent of each other) ----
    {
        int total = 8192 + L * 16384 + 4096;
        k_wconv<<<(total + 255) / 256, 256>>>(W_rel0, W_root0, W_rel_r, W_root_r, Wr1, ws, L);
    }
    k_zero_int<<<nb256, 256>>>(deg, N);
    k_hist<<<eb, 256>>>(ei, E, deg);
    k_scan_block<<<nb256, 256>>>(deg, excl, bsum, N);
    k_scan_sums<<<1, 512>>>(bsum, nb256);
    k_scan_add<<<nb256, 256>>>(excl, bsum, rowp, off, N, E);
    k_fill<<<eb, 256>>>(ei, ew, E, off, ssrc, sw);

    // ---- Layer 0 (64-d aggregate, K=64+64) ----
    k_agg64<<<(N + 7) / 8, 128>>>(x, rowp, ssrc, sw, agg, N);
    k_gemm_tc<128, 2, false><<<mb, 256, smem128>>>(agg, 64, x, 64, w0h, w0l, b0, y0, N, 0, nullptr, nullptr);

    // ---- Layers 1..L (128-d aggregate, K=128+128) ----
    float* yin = y0;
    float* yout = y1;
    for (int l = 0; l < L; l++) {
        uint32_t* wh = wrh + (size_t)l * 32768;
        uint32_t* wl = wh + 16384;
        const float* bl = b_r + (size_t)l * 128;
        k_agg128<<<(N + 3) / 4, 128>>>(yin, rowp, ssrc, sw, agg, N);
        k_gemm_tc<128, 2, false><<<mb, 256, smem128>>>(agg, 128, yin, 128, wh, wl, bl, yout, N, 0, nullptr, nullptr);
        float* t = yin; yin = yout; yout = t;
    }

    // ---- Readout (fused: GEMM + ReLU + dot(Wr2) + scatter-mean) ----
    k_zero_small<<<1, 1024>>>();
    k_gemm_tc<64, 1, true><<<mb, 256, smem64>>>(yin, 128, yin, 0, roh, rol, br1, nullptr, N, 1, Wr2, batch);
    k_div<<<4, 256>>>(br2, (float*)d_out);
}